// round 4
// baseline (speedup 1.0000x reference)
#include <cuda_runtime.h>
#include <cuda_bf16.h>
#include <math.h>

#define B 8
#define S 2048
#define D 2048
#define E 8
#define EPS 1e-5f

#define D4 (D / 4)            // 512 float4 per row
#define S_CHUNK 32            // rows per CTA
#define GX 2                  // D4 / 256
#define GY (S / S_CHUNK)      // 64
#define NBLK (GX * GY * B)    // 1024

// SoA partials: g_part[i][bid], i in 0..8 (8 expert dots + xsum), per batch b
// encoded in bid (bid -> b = bid / (GY*GX)). Fully overwritten each launch.
__device__ float g_part[9 * NBLK];
__device__ float g_stats[2 * E];             // [mean, scale] per expert
__device__ unsigned int g_ticket;

__global__ void __launch_bounds__(256) router_kernel(
    const float4* __restrict__ x4,
    const float4* __restrict__ W4,
    const float*  __restrict__ gain,
    const float*  __restrict__ init_std,
    const float*  __restrict__ noise,
    const int*    __restrict__ topk_p,
    float* __restrict__ out, int out_size)
{
    const int tid  = threadIdx.x;
    const int warp = tid >> 5, lane = tid & 31;
    const int d4   = blockIdx.x * 256 + tid;      // 0..511
    const int b    = blockIdx.z;
    const int s0   = blockIdx.y * S_CHUNK;
    const int bid  = (blockIdx.z * GY + blockIdx.y) * GX + blockIdx.x;

    __shared__ float s_red[9][8];

    // ---- stream x (evict-first): partial column sums over S_CHUNK rows ----
    const float4* p = x4 + ((size_t)b * S + s0) * D4 + d4;
    float4 acc = make_float4(0.f, 0.f, 0.f, 0.f);
#pragma unroll 8
    for (int i = 0; i < S_CHUNK; i++) {
        float4 v = __ldcs(&p[(size_t)i * D4]);
        acc.x += v.x; acc.y += v.y; acc.z += v.z; acc.w += v.w;
    }

    // ---- contract against W in-registers: 9 partials per thread ----
    float v9[9];
#pragma unroll
    for (int e = 0; e < E; e++) {
        float4 w = W4[e * D4 + d4];
        v9[e] = acc.x * w.x + acc.y * w.y + acc.z * w.z + acc.w * w.w;
    }
    v9[8] = acc.x + acc.y + acc.z + acc.w;        // xsum partial

    // ---- block reduce 9 values (warp shuffle + smem across 8 warps) ----
#pragma unroll
    for (int o = 16; o; o >>= 1)
#pragma unroll
        for (int i = 0; i < 9; i++)
            v9[i] += __shfl_xor_sync(0xFFFFFFFFu, v9[i], o);
    if (lane == 0)
#pragma unroll
        for (int i = 0; i < 9; i++) s_red[i][warp] = v9[i];
    __syncthreads();
    if (tid < 9) {
        float s = 0.f;
#pragma unroll
        for (int w = 0; w < 8; w++) s += s_red[tid][w];
        g_part[tid * NBLK + bid] = s;             // plain STG, no contention
    }

    // ---- first 8 blocks: per-expert W stats (L2-hot, overlapped) ----
    if (bid < E) {
        const int e = bid;
        const float4* wrow = W4 + e * D4;
        float s = 0.f, ss = 0.f;
#pragma unroll
        for (int i = 0; i < 2; i++) {
            float4 w = wrow[tid * 2 + i];
            s  += w.x + w.y + w.z + w.w;
            ss += w.x * w.x + w.y * w.y + w.z * w.z + w.w * w.w;
        }
#pragma unroll
        for (int o = 16; o; o >>= 1) {
            s  += __shfl_xor_sync(0xFFFFFFFFu, s,  o);
            ss += __shfl_xor_sync(0xFFFFFFFFu, ss, o);
        }
        __shared__ float s_s[8], s_ss[8];
        if (lane == 0) { s_s[warp] = s; s_ss[warp] = ss; }
        __syncthreads();
        if (tid == 0) {
            float ts = 0.f, tss = 0.f;
#pragma unroll
            for (int w = 0; w < 8; w++) { ts += s_s[w]; tss += s_ss[w]; }
            float mean = ts / (float)D;
            float var  = (tss - (float)D * mean * mean) / (float)(D - 1);
            float std  = sqrtf(fmaxf(var, 0.f)) + EPS;
            g_stats[2 * e]     = mean;
            g_stats[2 * e + 1] = init_std[e] / std * gain[e];
        }
    }

    // ---- last-block ticket: one fence, one atomic per CTA ----
    __syncthreads();
    __shared__ bool is_last;
    if (tid == 0) {
        __threadfence();
        unsigned t = atomicAdd(&g_ticket, 1u);
        is_last = (t == NBLK - 1);
    }
    __syncthreads();
    if (!is_last) return;

    // ================= finalize (one block) =================
    if (tid == 0) __threadfence();   // acquire-side ordering
    __syncthreads();

    // Reduce g_part: value i, batch b -> sum over GX*GY=128 bids.
    // bid range for batch b: [b*128, (b+1)*128). Warp w handles value i=w (0..7);
    // lane sums 128 floats as 1 float4 x ... : 128 values / 32 lanes = 4 each.
    __shared__ float s_dot[B * E], s_xsum[B], s_scale[E], s_mean[E];
    {
        // 8 warps x (9 values): warp w does value w for all batches, then warp 0
        // also does value 8. Each (value i, batch bb): 128 contiguous floats.
#pragma unroll
        for (int i = warp; i < 9; i += 8) {
            for (int bb = 0; bb < B; bb++) {
                const float4* q = (const float4*)(g_part + i * NBLK + bb * (GX * GY));
                float4 v = __ldcg(&q[lane]);            // 32 lanes x float4 = 128 floats
                float s = v.x + v.y + v.z + v.w;
#pragma unroll
                for (int o = 16; o; o >>= 1) s += __shfl_xor_sync(0xFFFFFFFFu, s, o);
                if (lane == 0) {
                    if (i < 8) s_dot[bb * E + i] = s;
                    else       s_xsum[bb] = s;
                }
            }
        }
    }
    if (tid < E) {
        s_mean[tid]  = __ldcg(&g_stats[2 * tid]);
        s_scale[tid] = __ldcg(&g_stats[2 * tid + 1]);
    }
    __syncthreads();

    if (tid < B) {
        const int bb = tid;
        int k = *topk_p;
        if (k > E) k = E;
        const float invS = 1.0f / (float)S;
        float sc[E];
        float mx = -INFINITY;
#pragma unroll
        for (int e = 0; e < E; e++) {
            float v = s_scale[e] * (s_dot[bb * E + e] - s_mean[e] * s_xsum[bb]) * invS
                      + noise[bb * E + e];
            sc[e] = v;
            mx = fmaxf(mx, v);
        }
        float denom = 0.f;
#pragma unroll
        for (int e = 0; e < E; e++) { sc[e] = expf(sc[e] - mx); denom += sc[e]; }
        float inv = 1.0f / denom;
#pragma unroll
        for (int e = 0; e < E; e++) sc[e] *= inv;

        float comb[E];
        bool taken[E];
#pragma unroll
        for (int e = 0; e < E; e++) { comb[e] = 0.f; taken[e] = false; }

        for (int kk = 0; kk < k; kk++) {
            int best = -1; float bv = -INFINITY;
            for (int e = 0; e < E; e++)
                if (!taken[e] && sc[e] > bv) { bv = sc[e]; best = e; }
            taken[best] = true;
            comb[best] = bv;
            int idx_off = B * E + bb * k + kk;
            int scr_off = B * E + B * k + bb * k + kk;
            if (idx_off < out_size) out[idx_off] = (float)best;
            if (scr_off < out_size) out[scr_off] = bv;
        }
#pragma unroll
        for (int e = 0; e < E; e++) {
            int o = bb * E + e;
            if (o < out_size) out[o] = comb[e];
        }
    }

    // reset ticket for next graph replay
    if (tid == 0) g_ticket = 0u;
}

extern "C" void kernel_launch(void* const* d_in, const int* in_sizes, int n_in,
                              void* d_out, int out_size) {
    const float* x        = (const float*)d_in[0];
    const float* W        = (const float*)d_in[1];
    const float* gain     = (const float*)d_in[2];
    const float* init_std = (const float*)d_in[3];
    const float* noise    = (const float*)d_in[4];
    const int*   topk     = (const int*)d_in[5];
    float* out = (float*)d_out;

    dim3 grid(GX, GY, B);
    router_kernel<<<grid, 256>>>((const float4*)x, (const float4*)W,
                                 gain, init_std, noise, topk, out, out_size);
}

// round 5
// speedup vs baseline: 1.1189x; 1.1189x over previous
#include <cuda_runtime.h>
#include <cuda_bf16.h>
#include <math.h>

#define B 8
#define S 2048
#define D 2048
#define E 8
#define EPS 1e-5f

#define D4 (D / 4)            // 512 float4 per row
#define S_CHUNK 32            // rows per CTA
#define GY (S / S_CHUNK)      // 64
#define NBLK (GY * B)         // 512
#define NW 16                 // warps per CTA (512 threads)
#define PAD 32                // one 128B line per accumulator

// Scratch, zero-init; finalizing block re-zeroes for graph replay.
__device__ float g_acc[(B * E + B) * PAD];
__device__ float g_stats[2 * E];
__device__ unsigned int g_ticket;

__global__ void __launch_bounds__(512) router_kernel(
    const float4* __restrict__ x4,
    const float4* __restrict__ W4,
    const float*  __restrict__ gain,
    const float*  __restrict__ init_std,
    const float*  __restrict__ noise,
    const int*    __restrict__ topk_p,
    float* __restrict__ out, int out_size)
{
    const int tid  = threadIdx.x;                 // 0..511 == d4
    const int warp = tid >> 5, lane = tid & 31;
    const int b    = blockIdx.y;
    const int s0   = blockIdx.x * S_CHUNK;
    const int bid  = blockIdx.y * GY + blockIdx.x;

    __shared__ float s_red[9][NW];

    // ---- stream x: each CTA reads full 8KB rows, fully contiguous ----
    const float4* p = x4 + ((size_t)b * S + s0) * D4 + tid;
    float4 acc = make_float4(0.f, 0.f, 0.f, 0.f);
#pragma unroll 8
    for (int i = 0; i < S_CHUNK; i++) {
        float4 v = p[(size_t)i * D4];
        acc.x += v.x; acc.y += v.y; acc.z += v.z; acc.w += v.w;
    }

    // ---- contract against W in-registers: 9 partials per thread ----
    float v9[9];
#pragma unroll
    for (int e = 0; e < E; e++) {
        float4 w = W4[e * D4 + tid];
        v9[e] = acc.x * w.x + acc.y * w.y + acc.z * w.z + acc.w * w.w;
    }
    v9[8] = acc.x + acc.y + acc.z + acc.w;        // xsum partial

    // ---- block reduce 9 values ----
#pragma unroll
    for (int o = 16; o; o >>= 1)
#pragma unroll
        for (int i = 0; i < 9; i++)
            v9[i] += __shfl_xor_sync(0xFFFFFFFFu, v9[i], o);
    if (lane == 0)
#pragma unroll
        for (int i = 0; i < 9; i++) s_red[i][warp] = v9[i];
    __syncthreads();
    if (tid < 9) {
        float s = 0.f;
#pragma unroll
        for (int w = 0; w < NW; w++) s += s_red[tid][w];
        int slot = (tid < 8) ? (b * E + tid) : (64 + b);
        atomicAdd(&g_acc[slot * PAD], s);
    }

    // ---- first 8 blocks: per-expert W stats (L2-hot, overlapped) ----
    if (bid < E) {
        const int e = bid;
        float4 w = W4[e * D4 + tid];              // 512 threads x 1 float4 = full row
        float s  = w.x + w.y + w.z + w.w;
        float ss = w.x * w.x + w.y * w.y + w.z * w.z + w.w * w.w;
#pragma unroll
        for (int o = 16; o; o >>= 1) {
            s  += __shfl_xor_sync(0xFFFFFFFFu, s,  o);
            ss += __shfl_xor_sync(0xFFFFFFFFu, ss, o);
        }
        __shared__ float s_s[NW], s_ss[NW];
        if (lane == 0) { s_s[warp] = s; s_ss[warp] = ss; }
        __syncthreads();
        if (tid == 0) {
            float ts = 0.f, tss = 0.f;
#pragma unroll
            for (int w2 = 0; w2 < NW; w2++) { ts += s_s[w2]; tss += s_ss[w2]; }
            float mean = ts / (float)D;
            float var  = (tss - (float)D * mean * mean) / (float)(D - 1);
            float std  = sqrtf(fmaxf(var, 0.f)) + EPS;
            g_stats[2 * e]     = mean;
            g_stats[2 * e + 1] = init_std[e] / std * gain[e];
        }
    }

    // ---- last-block ticket: one fence + one atomic per CTA ----
    __syncthreads();
    __shared__ bool is_last;
    if (tid == 0) {
        __threadfence();
        unsigned t = atomicAdd(&g_ticket, 1u);
        is_last = (t == NBLK - 1);
    }
    __syncthreads();
    if (!is_last) return;

    // ================= finalize (tiny) =================
    __shared__ float s_dot[B * E], s_xsum[B], s_scale[E], s_mean[E];
    if (tid < B * E) s_dot[tid]  = __ldcg(&g_acc[tid * PAD]);
    if (tid < B)     s_xsum[tid] = __ldcg(&g_acc[(64 + tid) * PAD]);
    if (tid < E) {
        s_mean[tid]  = __ldcg(&g_stats[2 * tid]);
        s_scale[tid] = __ldcg(&g_stats[2 * tid + 1]);
    }
    __syncthreads();

    if (tid < B) {
        const int bb = tid;
        int k = *topk_p;
        if (k > E) k = E;
        const float invS = 1.0f / (float)S;
        float sc[E];
        float mx = -INFINITY;
#pragma unroll
        for (int e = 0; e < E; e++) {
            float v = s_scale[e] * (s_dot[bb * E + e] - s_mean[e] * s_xsum[bb]) * invS
                      + noise[bb * E + e];
            sc[e] = v;
            mx = fmaxf(mx, v);
        }
        float denom = 0.f;
#pragma unroll
        for (int e = 0; e < E; e++) { sc[e] = expf(sc[e] - mx); denom += sc[e]; }
        float inv = 1.0f / denom;
#pragma unroll
        for (int e = 0; e < E; e++) sc[e] *= inv;

        float comb[E];
        bool taken[E];
#pragma unroll
        for (int e = 0; e < E; e++) { comb[e] = 0.f; taken[e] = false; }

        for (int kk = 0; kk < k; kk++) {
            int best = -1; float bv = -INFINITY;
            for (int e = 0; e < E; e++)
                if (!taken[e] && sc[e] > bv) { bv = sc[e]; best = e; }
            taken[best] = true;
            comb[best] = bv;
            int idx_off = B * E + bb * k + kk;
            int scr_off = B * E + B * k + bb * k + kk;
            if (idx_off < out_size) out[idx_off] = (float)best;
            if (scr_off < out_size) out[scr_off] = bv;
        }
#pragma unroll
        for (int e = 0; e < E; e++) {
            int o = bb * E + e;
            if (o < out_size) out[o] = comb[e];
        }
    }
    __syncthreads();

    // reset scratch for next graph replay
    if (tid < B * E + B) g_acc[tid * PAD] = 0.f;
    if (tid == 0) g_ticket = 0u;
}

extern "C" void kernel_launch(void* const* d_in, const int* in_sizes, int n_in,
                              void* d_out, int out_size) {
    const float* x        = (const float*)d_in[0];
    const float* W        = (const float*)d_in[1];
    const float* gain     = (const float*)d_in[2];
    const float* init_std = (const float*)d_in[3];
    const float* noise    = (const float*)d_in[4];
    const int*   topk     = (const int*)d_in[5];
    float* out = (float*)d_out;

    dim3 grid(GY, B);
    router_kernel<<<grid, 512>>>((const float4*)x, (const float4*)W,
                                 gain, init_std, noise, topk, out, out_size);
}

// round 7
// speedup vs baseline: 1.1670x; 1.0430x over previous
#include <cuda_runtime.h>
#include <cuda_bf16.h>
#include <math.h>

#define B 8
#define S 2048
#define D 2048
#define E 8
#define EPS 1e-5f

#define D4 (D / 4)            // 512 float4 per row
#define D8 (D / 8)            // 256 32B-chunks per row
#define S_CHUNK 32            // rows per CTA
#define GY (S / S_CHUNK)      // 64
#define NBLK (GY * B)         // 512

// Scratch, zero-init; finalizing block re-zeroes for graph replay.
__device__ float g_acc[B * E + B];
__device__ unsigned int g_ticket;

// 32-byte x load with L2 evict_last (ptxas requires .v8.b32 for this policy).
__device__ __forceinline__ void ldg_el8(const float* p, float4& a, float4& b) {
    unsigned r0, r1, r2, r3, r4, r5, r6, r7;
    asm volatile("ld.global.nc.L2::evict_last.v8.b32 {%0,%1,%2,%3,%4,%5,%6,%7}, [%8];"
                 : "=r"(r0), "=r"(r1), "=r"(r2), "=r"(r3),
                   "=r"(r4), "=r"(r5), "=r"(r6), "=r"(r7)
                 : "l"(p));
    a.x = __uint_as_float(r0); a.y = __uint_as_float(r1);
    a.z = __uint_as_float(r2); a.w = __uint_as_float(r3);
    b.x = __uint_as_float(r4); b.y = __uint_as_float(r5);
    b.z = __uint_as_float(r6); b.w = __uint_as_float(r7);
}

__global__ void __launch_bounds__(256) router_kernel(
    const float*  __restrict__ x,
    const float4* __restrict__ W4,
    const float*  __restrict__ gain,
    const float*  __restrict__ init_std,
    const float*  __restrict__ noise,
    const int*    __restrict__ topk_p,
    float* __restrict__ out, int out_size)
{
    const int tid  = threadIdx.x;                 // 0..255 == 32B-chunk index
    const int warp = tid >> 5, lane = tid & 31;
    const int b    = blockIdx.y;
    const int s0   = blockIdx.x * S_CHUNK;
    const int bid  = blockIdx.y * GY + blockIdx.x;

    // ---- stream x (evict_last, 32B loads): full 8KB row per iteration ----
    const float* p = x + ((size_t)b * S + s0) * D + tid * 8;
    float4 acc0 = make_float4(0.f, 0.f, 0.f, 0.f);
    float4 acc1 = make_float4(0.f, 0.f, 0.f, 0.f);
#pragma unroll 8
    for (int i = 0; i < S_CHUNK; i++) {
        float4 a, c;
        ldg_el8(p + (size_t)i * D, a, c);
        acc0.x += a.x; acc0.y += a.y; acc0.z += a.z; acc0.w += a.w;
        acc1.x += c.x; acc1.y += c.y; acc1.z += c.z; acc1.w += c.w;
    }

    // ---- contract against W in-registers: 9 partials per thread ----
    float v9[9];
#pragma unroll
    for (int e = 0; e < E; e++) {
        float4 w0 = W4[e * D4 + tid * 2];
        float4 w1 = W4[e * D4 + tid * 2 + 1];
        v9[e] = acc0.x * w0.x + acc0.y * w0.y + acc0.z * w0.z + acc0.w * w0.w
              + acc1.x * w1.x + acc1.y * w1.y + acc1.z * w1.z + acc1.w * w1.w;
    }
    v9[8] = acc0.x + acc0.y + acc0.z + acc0.w
          + acc1.x + acc1.y + acc1.z + acc1.w;    // xsum partial

    // ---- block reduce 9 values ----
    __shared__ float s_red[9][8];
#pragma unroll
    for (int o = 16; o; o >>= 1)
#pragma unroll
        for (int i = 0; i < 9; i++)
            v9[i] += __shfl_xor_sync(0xFFFFFFFFu, v9[i], o);
    if (lane == 0)
#pragma unroll
        for (int i = 0; i < 9; i++) s_red[i][warp] = v9[i];
    __syncthreads();
    if (tid < 9) {
        float s = 0.f;
#pragma unroll
        for (int w = 0; w < 8; w++) s += s_red[tid][w];
        atomicAdd(&g_acc[tid < 8 ? b * E + tid : 64 + b], s);
    }

    // ---- last-block ticket ----
    __threadfence();
    __shared__ bool is_last;
    if (tid == 0) {
        unsigned t = atomicAdd(&g_ticket, 1u);
        is_last = (t == NBLK - 1);
    }
    __syncthreads();
    if (!is_last) return;

    // ================= finalize (one block) =================
    __shared__ float s_dot[B * E], s_xsum[B], s_scale[E], s_mean[E];
    if (tid < B * E) s_dot[tid] = __ldcg(&g_acc[tid]);
    if (tid < B)     s_xsum[tid] = __ldcg(&g_acc[64 + tid]);

    // per-expert W stats: warp e -> expert e (float4 loads, 16 per lane)
    {
        const float4* wrow = W4 + warp * D4;
        float s = 0.f, ss = 0.f;
#pragma unroll 4
        for (int i = lane; i < D4; i += 32) {
            float4 w = wrow[i];
            s  += w.x + w.y + w.z + w.w;
            ss += w.x * w.x + w.y * w.y + w.z * w.z + w.w * w.w;
        }
#pragma unroll
        for (int o = 16; o; o >>= 1) {
            s  += __shfl_xor_sync(0xFFFFFFFFu, s,  o);
            ss += __shfl_xor_sync(0xFFFFFFFFu, ss, o);
        }
        if (lane == 0) {
            float mean = s / (float)D;
            float var  = (ss - (float)D * mean * mean) / (float)(D - 1);
            float std  = sqrtf(fmaxf(var, 0.f)) + EPS;
            s_mean[warp]  = mean;
            s_scale[warp] = init_std[warp] / std * gain[warp];
        }
    }
    __syncthreads();

    // per-batch softmax + top-k
    if (tid < B) {
        const int bb = tid;
        int k = *topk_p;
        if (k > E) k = E;
        const float invS = 1.0f / (float)S;
        float sc[E];
        float mx = -INFINITY;
#pragma unroll
        for (int e = 0; e < E; e++) {
            float v = s_scale[e] * (s_dot[bb * E + e] - s_mean[e] * s_xsum[bb]) * invS
                      + noise[bb * E + e];
            sc[e] = v;
            mx = fmaxf(mx, v);
        }
        float denom = 0.f;
#pragma unroll
        for (int e = 0; e < E; e++) { sc[e] = expf(sc[e] - mx); denom += sc[e]; }
        float inv = 1.0f / denom;
#pragma unroll
        for (int e = 0; e < E; e++) sc[e] *= inv;

        float comb[E];
        bool taken[E];
#pragma unroll
        for (int e = 0; e < E; e++) { comb[e] = 0.f; taken[e] = false; }

        for (int kk = 0; kk < k; kk++) {
            int best = -1; float bv = -INFINITY;
            for (int e = 0; e < E; e++)
                if (!taken[e] && sc[e] > bv) { bv = sc[e]; best = e; }
            taken[best] = true;
            comb[best] = bv;
            int idx_off = B * E + bb * k + kk;
            int scr_off = B * E + B * k + bb * k + kk;
            if (idx_off < out_size) out[idx_off] = (float)best;
            if (scr_off < out_size) out[scr_off] = bv;
        }
#pragma unroll
        for (int e = 0; e < E; e++) {
            int o = bb * E + e;
            if (o < out_size) out[o] = comb[e];
        }
    }
    __syncthreads();

    // reset scratch for the next graph replay
    if (tid < B * E + B) g_acc[tid] = 0.f;
    if (tid == 0) g_ticket = 0u;
}

extern "C" void kernel_launch(void* const* d_in, const int* in_sizes, int n_in,
                              void* d_out, int out_size) {
    const float* x        = (const float*)d_in[0];
    const float* W        = (const float*)d_in[1];
    const float* gain     = (const float*)d_in[2];
    const float* init_std = (const float*)d_in[3];
    const float* noise    = (const float*)d_in[4];
    const int*   topk     = (const int*)d_in[5];
    float* out = (float*)d_out;

    dim3 grid(GY, B);
    router_kernel<<<grid, 256>>>(x, (const float4*)W,
                                 gain, init_std, noise, topk, out, out_size);
}